// round 3
// baseline (speedup 1.0000x reference)
#include <cuda_runtime.h>
#include <cuda.h>
#include <cstdint>

// ---------------- problem constants ----------------
#define NN     10000
#define CC     128
#define NADJ   3
#define NSLOPE 0.2f

#define KCH     32
#define NCHUNK  ((NN + KCH - 1) / KCH)      // 313
#define NSPLIT  8                           // split-K factor
#define MTILES  ((NN + 127) / 128)          // 79
#define MPAD    (MTILES * 128)              // 10112

#define TILE_BYTES  (128 * KCH * 4)         // 16 KB
#define STAGE_BYTES (4 * TILE_BYTES)        // 3 A tiles + 1 B tile = 64 KB
#define STAGES      3
#define DYNSMEM     (STAGES * STAGE_BYTES + 1024)

// scratch (static device arrays — no allocation)
__device__ __align__(1024) float g_sup_t[CC * NN];             // supᵀ, tf32-rounded
__device__ __align__(16)   float g_part[NSPLIT][MPAD][CC];     // split-K partials

// ---------------- helpers ----------------
__device__ __forceinline__ uint32_t smem_u32(const void* p) {
    uint32_t a;
    asm("{ .reg .u64 t; cvta.to.shared.u64 t, %1; cvt.u32.u64 %0, t; }" : "=r"(a) : "l"(p));
    return a;
}
__device__ __forceinline__ float tf32_rna_f(float x) {
    uint32_t u;
    asm("cvt.rna.tf32.f32 %0, %1;" : "=r"(u) : "f"(x));
    return __uint_as_float(u);
}
__device__ __forceinline__ uint32_t f2tf32(float x) {
    uint32_t u;
    asm("cvt.rna.tf32.f32 %0, %1;" : "=r"(u) : "f"(x));
    return u;
}
__device__ __forceinline__ float lds_f32(uint32_t a) {
    float v;
    asm volatile("ld.shared.f32 %0, [%1];" : "=f"(v) : "r"(a));
    return v;
}
__device__ __forceinline__ uint32_t lds_b32(uint32_t a) {
    uint32_t v;
    asm volatile("ld.shared.b32 %0, [%1];" : "=r"(v) : "r"(a));
    return v;
}

#define MBARRIER_INIT(addr, cnt) \
    asm volatile("mbarrier.init.shared.b64 [%0], %1;" :: "r"(addr), "r"(cnt) : "memory")
#define MBARRIER_EXPECT_TX(addr, bytes) \
    asm volatile("mbarrier.arrive.expect_tx.shared.b64 _, [%0], %1;" :: "r"(addr), "r"(bytes) : "memory")
#define MBARRIER_ARRIVE(addr) \
    asm volatile("mbarrier.arrive.shared.b64 _, [%0];" :: "r"(addr) : "memory")

#define MBARRIER_WAIT_PARITY(mbar, par) do {                                      \
    uint32_t _m = (mbar), _p = (par), _d;                                         \
    asm volatile("{\n\t.reg .pred p;\n\t"                                         \
        "mbarrier.try_wait.parity.acquire.cta.shared::cta.b64 p, [%1], %2;\n\t"   \
        "selp.b32 %0, 1, 0, p;\n\t}" : "=r"(_d) : "r"(_m), "r"(_p) : "memory");   \
    if (!_d) {                                                                    \
        asm volatile("{\n\t.reg .pred P1;\n\t"                                    \
            "W_%=:\n\t"                                                           \
            "mbarrier.try_wait.parity.acquire.cta.shared::cta.b64 P1, [%0], %1, 0x989680;\n\t" \
            "@P1 bra.uni D_%=;\n\t"                                               \
            "bra.uni W_%=;\n\t"                                                   \
            "D_%=:\n\t}" :: "r"(_m), "r"(_p) : "memory");                         \
    } } while (0)

#define MBARRIER_WAIT_PARITY_RELAXED(mbar, par) do {                              \
    uint32_t _m = (mbar), _p = (par), _d;                                         \
    asm volatile("{\n\t.reg .pred p;\n\t"                                         \
        "mbarrier.try_wait.parity.relaxed.cta.shared::cta.b64 p, [%1], %2, 0x989680;\n\t" \
        "selp.b32 %0, 1, 0, p;\n\t}" : "=r"(_d) : "r"(_m), "r"(_p) : "memory");   \
    if (!_d) {                                                                    \
        asm volatile("{\n\t.reg .pred P1;\n\t"                                    \
            "W_%=:\n\t"                                                           \
            "mbarrier.try_wait.parity.relaxed.cta.shared::cta.b64 P1, [%0], %1, 0x989680;\n\t" \
            "@P1 bra.uni D_%=;\n\t"                                               \
            "bra.uni W_%=;\n\t"                                                   \
            "D_%=:\n\t}" :: "r"(_m), "r"(_p) : "memory");                         \
    } } while (0)

#define TMA_LOAD_3D(sa, tmap, x, y, z, mbar)                                      \
    asm volatile("cp.async.bulk.tensor.3d.shared::cta.global.tile.mbarrier::complete_tx::bytes " \
        "[%0], [%1, {%2, %3, %4}], [%5];"                                         \
        :: "r"((uint32_t)(sa)), "l"(tmap), "r"((int)(x)), "r"((int)(y)),          \
           "r"((int)(z)), "r"((uint32_t)(mbar)) : "memory")

// mma.sync m16n8k8 tf32 (baseline PTX, works at compute_103)
__device__ __forceinline__ void mma_tf32(float* c, const uint32_t* A,
                                         uint32_t b0, uint32_t b1) {
    asm volatile(
        "mma.sync.aligned.m16n8k8.row.col.f32.tf32.tf32.f32 "
        "{%0,%1,%2,%3}, {%4,%5,%6,%7}, {%8,%9}, {%0,%1,%2,%3};"
        : "+f"(c[0]), "+f"(c[1]), "+f"(c[2]), "+f"(c[3])
        : "r"(A[0]), "r"(A[1]), "r"(A[2]), "r"(A[3]), "r"(b0), "r"(b1));
}

// ---------------- kernel 1: support = X@W + b ; write transposed tf32 copy --------
// 8 rows / block, 1250 blocks -> ~34 warps/SM (was 8.5 -> occ fix)
__global__ void __launch_bounds__(128)
k_support(const float* __restrict__ inp, const float* __restrict__ w,
          const float* __restrict__ b) {
    __shared__ float in_s[8][CC];
    __shared__ float s_out[CC][9];     // padded transpose buffer
    const int t  = threadIdx.x;        // = output channel c
    const int n0 = blockIdx.x * 8;

    #pragma unroll
    for (int j = 0; j < 8; ++j)
        in_s[j][t] = inp[(n0 + j) * CC + t];   // NN % 8 == 0, always in-bounds
    __syncthreads();

    float acc[8];
    #pragma unroll
    for (int j = 0; j < 8; ++j) acc[j] = 0.f;
    const float bc = b[t];
    #pragma unroll 4
    for (int i = 0; i < CC; ++i) {
        const float wv = w[i * CC + t];
        #pragma unroll
        for (int j = 0; j < 8; ++j) acc[j] = fmaf(in_s[j][i], wv, acc[j]);
    }
    #pragma unroll
    for (int j = 0; j < 8; ++j) s_out[t][j] = acc[j] + bc;
    __syncthreads();

    // coalesced transposed store: lanes cover 8 consecutive n per channel
    const int j2 = t & 7;
    const int c0 = t >> 3;             // 16 channels per pass
    #pragma unroll
    for (int cc = 0; cc < CC; cc += 16)
        g_sup_t[(cc + c0) * NN + n0 + j2] = tf32_rna_f(s_out[cc + c0][j2]);
}

// ---------------- kernel 2: split-K tf32 HMMA GEMM with register adjacency premix ----
__global__ void __launch_bounds__(256, 1)
k_gemm(const __grid_constant__ CUtensorMap tmap_a,
       const __grid_constant__ CUtensorMap tmap_b,
       const float* __restrict__ att) {
    extern __shared__ __align__(1024) char dsm[];
    __shared__ __align__(8) uint64_t bars[2 * STAGES];

    const int tid  = threadIdx.x;
    const int wid  = tid >> 5;
    const int lane = tid & 31;
    const int g    = lane >> 2;        // group id 0..7
    const int q    = lane & 3;         // thread-in-group
    const int m0   = blockIdx.x * 128;
    const int sidx = blockIdx.y;       // K split index

    const uint32_t dbase = (smem_u32(dsm) + 1023u) & ~1023u;
    const uint32_t barb  = smem_u32(bars);
    // full[s] at barb + 8*s ; empty[s] at barb + 8*(STAGES+s)

    if (tid == 0) {
        for (int s = 0; s < STAGES; ++s) {
            MBARRIER_INIT(barb + 8 * s, 1);
            MBARRIER_INIT(barb + 8 * (STAGES + s), 256);
        }
        asm volatile("fence.proxy.async.shared::cta;" ::: "memory");
    }
    __syncthreads();

    const float at0 = att[0], at1 = att[1], at2 = att[2];
    const int nch = (NCHUNK - sidx + NSPLIT - 1) / NSPLIT;   // chunks for this split

    // ---- producer prologue: fill all stages ----
    if (tid == 0) {
        int pre = (nch < STAGES) ? nch : STAGES;
        for (int i = 0; i < pre; ++i) {
            uint32_t fb = barb + 8 * i;
            uint32_t sb = dbase + i * STAGE_BYTES;
            MBARRIER_EXPECT_TX(fb, (uint32_t)STAGE_BYTES);
            int k0 = (sidx + i * NSPLIT) * KCH;
            #pragma unroll
            for (int t = 0; t < NADJ; ++t)
                TMA_LOAD_3D(sb + t * TILE_BYTES, &tmap_a, k0, m0, t, fb);
            TMA_LOAD_3D(sb + 3 * TILE_BYTES, &tmap_b, k0, 0, 0, fb);
        }
    }

    float acc[2][8][4];
    #pragma unroll
    for (int mi = 0; mi < 2; ++mi)
        #pragma unroll
        for (int ni = 0; ni < 8; ++ni)
            #pragma unroll
            for (int r = 0; r < 4; ++r) acc[mi][ni][r] = 0.f;

    const int wm = wid & 3;            // M sub-tile 0..3 (32 rows each)
    const int wn = wid >> 2;           // N sub-tile 0..1 (64 cols each)
    const uint32_t xo = (uint32_t)g << 2;  // swizzle xor term, in words

    for (int it = 0; it < nch; ++it) {
        const int s  = it % STAGES;
        const int ph = (it / STAGES) & 1;
        MBARRIER_WAIT_PARITY(barb + 8 * s, ph);

        const uint32_t sb = dbase + s * STAGE_BYTES;
        const uint32_t Bb = sb + 3 * TILE_BYTES;

        #pragma unroll
        for (int ks = 0; ks < 4; ++ks) {
            const uint32_t k0x = ((uint32_t)(ks * 8 + q))     ^ xo;
            const uint32_t k1x = ((uint32_t)(ks * 8 + q + 4)) ^ xo;

            // ---- load 3 adjacency fragment sets, premix, round to tf32 ----
            uint32_t amix[2][4];
            #pragma unroll
            for (int mi = 0; mi < 2; ++mi) {
                const uint32_t rw = (uint32_t)((wm * 32 + mi * 16 + g) * 32);
                uint32_t w0 = (rw + k0x) * 4;           // (g,   q)
                uint32_t w1 = (rw + 256 + k0x) * 4;     // (g+8, q)
                uint32_t w2 = (rw + k1x) * 4;           // (g,   q+4)
                uint32_t w3 = (rw + 256 + k1x) * 4;     // (g+8, q+4)
                #pragma unroll
                for (int p = 0; p < 4; ++p) {
                    uint32_t wp = (p == 0) ? w0 : (p == 1) ? w1 : (p == 2) ? w2 : w3;
                    float v = at0 * lds_f32(sb + wp);
                    v = fmaf(at1, lds_f32(sb + TILE_BYTES + wp), v);
                    v = fmaf(at2, lds_f32(sb + 2 * TILE_BYTES + wp), v);
                    amix[mi][p] = f2tf32(v);
                }
            }

            // ---- B fragments + MMA ----
            #pragma unroll
            for (int ni = 0; ni < 8; ++ni) {
                const uint32_t cw = (uint32_t)((wn * 64 + ni * 8 + g) * 32);
                uint32_t b0 = lds_b32(Bb + (cw + k0x) * 4);
                uint32_t b1 = lds_b32(Bb + (cw + k1x) * 4);
                mma_tf32(acc[0][ni], amix[0], b0, b1);
                mma_tf32(acc[1][ni], amix[1], b0, b1);
            }
        }

        MBARRIER_ARRIVE(barb + 8 * (STAGES + s));

        if (tid == 0 && it + STAGES < nch) {
            MBARRIER_WAIT_PARITY_RELAXED(barb + 8 * (STAGES + s), (it / STAGES) & 1);
            uint32_t fb = barb + 8 * s;
            MBARRIER_EXPECT_TX(fb, (uint32_t)STAGE_BYTES);
            int k0 = (sidx + (it + STAGES) * NSPLIT) * KCH;
            #pragma unroll
            for (int t = 0; t < NADJ; ++t)
                TMA_LOAD_3D(sb + t * TILE_BYTES, &tmap_a, k0, m0, t, fb);
            TMA_LOAD_3D(sb + 3 * TILE_BYTES, &tmap_b, k0, 0, 0, fb);
        }
    }

    // ---- write split-K partials ----
    float* pbase = &g_part[sidx][0][0];
    #pragma unroll
    for (int mi = 0; mi < 2; ++mi) {
        #pragma unroll
        for (int ni = 0; ni < 8; ++ni) {
            int r = m0 + wm * 32 + mi * 16 + g;
            int c = wn * 64 + ni * 8 + q * 2;
            float2 v0 = make_float2(acc[mi][ni][0], acc[mi][ni][1]);
            float2 v1 = make_float2(acc[mi][ni][2], acc[mi][ni][3]);
            *reinterpret_cast<float2*>(pbase + (size_t)r * CC + c)       = v0;
            *reinterpret_cast<float2*>(pbase + (size_t)(r + 8) * CC + c) = v1;
        }
    }
}

// ---------------- kernel 3: reduce split-K partials + LeakyReLU --------------------
__global__ void __launch_bounds__(256)
k_reduce(float* __restrict__ out) {
    const int idx = blockIdx.x * 256 + threadIdx.x;   // one float4 each
    const int total = NN * CC / 4;
    if (idx >= total) return;
    const int n  = idx / (CC / 4);
    const int c4 = (idx % (CC / 4)) * 4;

    float4 s = make_float4(0.f, 0.f, 0.f, 0.f);
    #pragma unroll
    for (int k = 0; k < NSPLIT; ++k) {
        const float4 v = *reinterpret_cast<const float4*>(&g_part[k][n][c4]);
        s.x += v.x; s.y += v.y; s.z += v.z; s.w += v.w;
    }
    s.x = (s.x >= 0.f) ? s.x : NSLOPE * s.x;
    s.y = (s.y >= 0.f) ? s.y : NSLOPE * s.y;
    s.z = (s.z >= 0.f) ? s.z : NSLOPE * s.z;
    s.w = (s.w >= 0.f) ? s.w : NSLOPE * s.w;
    *reinterpret_cast<float4*>(&out[(size_t)n * CC + c4]) = s;
}

// ---------------- host launch ----------------
typedef CUresult (*PFN_encodeTiled)(
    CUtensorMap*, CUtensorMapDataType, cuuint32_t, void*,
    const cuuint64_t*, const cuuint64_t*, const cuuint32_t*, const cuuint32_t*,
    CUtensorMapInterleave, CUtensorMapSwizzle, CUtensorMapL2promotion,
    CUtensorMapFloatOOBfill);

extern "C" void kernel_launch(void* const* d_in, const int* in_sizes, int n_in,
                              void* d_out, int out_size) {
    const float *inp = nullptr, *adj = nullptr, *att = nullptr, *w = nullptr, *b = nullptr;
    for (int i = 0; i < n_in; ++i) {
        switch (in_sizes[i]) {
            case NN * CC:        inp = (const float*)d_in[i]; break;
            case NADJ * NN * NN: adj = (const float*)d_in[i]; break;
            case NADJ:           att = (const float*)d_in[i]; break;
            case CC * CC:        w   = (const float*)d_in[i]; break;
            case CC:             b   = (const float*)d_in[i]; break;
            default: break;
        }
    }
    float* out = (float*)d_out;

    k_support<<<NN / 8, 128>>>(inp, w, b);

    PFN_encodeTiled enc = nullptr;
    {
        void* p = nullptr;
        cudaDriverEntryPointQueryResult st;
#if CUDART_VERSION >= 12050
        cudaGetDriverEntryPointByVersion("cuTensorMapEncodeTiled", &p, 12000,
                                         cudaEnableDefault, &st);
#else
        cudaGetDriverEntryPoint("cuTensorMapEncodeTiled", &p, cudaEnableDefault, &st);
#endif
        enc = (PFN_encodeTiled)p;
    }
    void* supt_ptr = nullptr;
    cudaGetSymbolAddress(&supt_ptr, g_sup_t);

    CUtensorMap ta, tb;
    cuuint32_t box[3] = {KCH, 128, 1};
    cuuint32_t es[3]  = {1, 1, 1};
    {   // A: adj_set [NADJ][NN][NN], inner dim = K (n_in)
        cuuint64_t dims[3] = {NN, NN, NADJ};
        cuuint64_t str[2]  = {(cuuint64_t)NN * 4, (cuuint64_t)NN * NN * 4};
        enc(&ta, CU_TENSOR_MAP_DATA_TYPE_FLOAT32, 3, (void*)adj, dims, str, box, es,
            CU_TENSOR_MAP_INTERLEAVE_NONE, CU_TENSOR_MAP_SWIZZLE_128B,
            CU_TENSOR_MAP_L2_PROMOTION_L2_128B, CU_TENSOR_MAP_FLOAT_OOB_FILL_NONE);
    }
    {   // B: g_sup_t [CC][NN], inner dim = K (n)
        cuuint64_t dims[3] = {NN, CC, 1};
        cuuint64_t str[2]  = {(cuuint64_t)NN * 4, (cuuint64_t)CC * NN * 4};
        enc(&tb, CU_TENSOR_MAP_DATA_TYPE_FLOAT32, 3, supt_ptr, dims, str, box, es,
            CU_TENSOR_MAP_INTERLEAVE_NONE, CU_TENSOR_MAP_SWIZZLE_128B,
            CU_TENSOR_MAP_L2_PROMOTION_L2_128B, CU_TENSOR_MAP_FLOAT_OOB_FILL_NONE);
    }

    cudaFuncSetAttribute(k_gemm, cudaFuncAttributeMaxDynamicSharedMemorySize, DYNSMEM);
    dim3 grid(MTILES, NSPLIT);
    k_gemm<<<grid, 256, DYNSMEM>>>(ta, tb, att);

    k_reduce<<<(NN * CC / 4 + 255) / 256, 256>>>(out);
}

// round 4
// speedup vs baseline: 1.0083x; 1.0083x over previous
#include <cuda_runtime.h>
#include <cuda.h>
#include <cstdint>

// ---------------- problem constants ----------------
#define NN     10000
#define CC     128
#define NADJ   3
#define NSLOPE 0.2f

#define KCH     32
#define NCHUNK  ((NN + KCH - 1) / KCH)      // 313
#define NSPLIT  11                          // 79*11=869 CTAs -> 6 waves @ 97.9% fill
#define MTILES  ((NN + 127) / 128)          // 79
#define MPAD    (MTILES * 128)              // 10112

#define TILE_BYTES  (128 * KCH * 4)         // 16 KB
#define STAGE_BYTES (4 * TILE_BYTES)        // 3 A tiles + 1 B tile = 64 KB
#define STAGES      3
#define DYNSMEM     (STAGES * STAGE_BYTES + 1024)

// scratch (static device arrays — no allocation)
__device__ __align__(1024) float g_sup_t[CC * NN];             // supᵀ, tf32, k-pair permuted
__device__ __align__(16)   float g_part[NSPLIT][MPAD][CC];     // split-K partials

// ---------------- helpers ----------------
__device__ __forceinline__ uint32_t smem_u32(const void* p) {
    uint32_t a;
    asm("{ .reg .u64 t; cvta.to.shared.u64 t, %1; cvt.u32.u64 %0, t; }" : "=r"(a) : "l"(p));
    return a;
}
__device__ __forceinline__ float tf32_rna_f(float x) {
    uint32_t u;
    asm("cvt.rna.tf32.f32 %0, %1;" : "=r"(u) : "f"(x));
    return __uint_as_float(u);
}
__device__ __forceinline__ uint32_t f2tf32(float x) {
    uint32_t u;
    asm("cvt.rna.tf32.f32 %0, %1;" : "=r"(u) : "f"(x));
    return u;
}
__device__ __forceinline__ float lds_f32(uint32_t a) {
    float v;
    asm volatile("ld.shared.f32 %0, [%1];" : "=f"(v) : "r"(a));
    return v;
}
__device__ __forceinline__ void lds_b64(uint32_t a, uint32_t& lo, uint32_t& hi) {
    asm volatile("ld.shared.v2.b32 {%0, %1}, [%2];" : "=r"(lo), "=r"(hi) : "r"(a));
}

#define MBARRIER_INIT(addr, cnt) \
    asm volatile("mbarrier.init.shared.b64 [%0], %1;" :: "r"(addr), "r"(cnt) : "memory")
#define MBARRIER_EXPECT_TX(addr, bytes) \
    asm volatile("mbarrier.arrive.expect_tx.shared.b64 _, [%0], %1;" :: "r"(addr), "r"(bytes) : "memory")
#define MBARRIER_ARRIVE(addr) \
    asm volatile("mbarrier.arrive.shared.b64 _, [%0];" :: "r"(addr) : "memory")

#define MBARRIER_WAIT_PARITY(mbar, par) do {                                      \
    uint32_t _m = (mbar), _p = (par), _d;                                         \
    asm volatile("{\n\t.reg .pred p;\n\t"                                         \
        "mbarrier.try_wait.parity.acquire.cta.shared::cta.b64 p, [%1], %2;\n\t"   \
        "selp.b32 %0, 1, 0, p;\n\t}" : "=r"(_d) : "r"(_m), "r"(_p) : "memory");   \
    if (!_d) {                                                                    \
        asm volatile("{\n\t.reg .pred P1;\n\t"                                    \
            "W_%=:\n\t"                                                           \
            "mbarrier.try_wait.parity.acquire.cta.shared::cta.b64 P1, [%0], %1, 0x989680;\n\t" \
            "@P1 bra.uni D_%=;\n\t"                                               \
            "bra.uni W_%=;\n\t"                                                   \
            "D_%=:\n\t}" :: "r"(_m), "r"(_p) : "memory");                         \
    } } while (0)

#define MBARRIER_WAIT_PARITY_RELAXED(mbar, par) do {                              \
    uint32_t _m = (mbar), _p = (par), _d;                                         \
    asm volatile("{\n\t.reg .pred p;\n\t"                                         \
        "mbarrier.try_wait.parity.relaxed.cta.shared::cta.b64 p, [%1], %2, 0x989680;\n\t" \
        "selp.b32 %0, 1, 0, p;\n\t}" : "=r"(_d) : "r"(_m), "r"(_p) : "memory");   \
    if (!_d) {                                                                    \
        asm volatile("{\n\t.reg .pred P1;\n\t"                                    \
            "W_%=:\n\t"                                                           \
            "mbarrier.try_wait.parity.relaxed.cta.shared::cta.b64 P1, [%0], %1, 0x989680;\n\t" \
            "@P1 bra.uni D_%=;\n\t"                                               \
            "bra.uni W_%=;\n\t"                                                   \
            "D_%=:\n\t}" :: "r"(_m), "r"(_p) : "memory");                         \
    } } while (0)

#define TMA_LOAD_3D(sa, tmap, x, y, z, mbar)                                      \
    asm volatile("cp.async.bulk.tensor.3d.shared::cta.global.tile.mbarrier::complete_tx::bytes " \
        "[%0], [%1, {%2, %3, %4}], [%5];"                                         \
        :: "r"((uint32_t)(sa)), "l"(tmap), "r"((int)(x)), "r"((int)(y)),          \
           "r"((int)(z)), "r"((uint32_t)(mbar)) : "memory")

// mma.sync m16n8k8 tf32 (baseline PTX, works at compute_103)
__device__ __forceinline__ void mma_tf32(float* c, const uint32_t* A,
                                         uint32_t b0, uint32_t b1) {
    asm volatile(
        "mma.sync.aligned.m16n8k8.row.col.f32.tf32.tf32.f32 "
        "{%0,%1,%2,%3}, {%4,%5,%6,%7}, {%8,%9}, {%0,%1,%2,%3};"
        : "+f"(c[0]), "+f"(c[1]), "+f"(c[2]), "+f"(c[3])
        : "r"(A[0]), "r"(A[1]), "r"(A[2]), "r"(A[3]), "r"(b0), "r"(b1));
}

// ---------------- kernel 1: support = X@W + b ; transposed tf32 copy, k-pair permuted ----
// 16 rows/block, 625 blocks; within each 8-block of n, store order (0,4,1,5,2,6,3,7)
// so the GEMM's B fragment pair (k, k+4) is one 8-byte shared load.
__global__ void __launch_bounds__(128)
k_support(const float* __restrict__ inp, const float* __restrict__ w,
          const float* __restrict__ b) {
    __shared__ float in_s[16][CC];
    __shared__ float s_out[CC][17];    // padded transpose buffer
    const int t  = threadIdx.x;        // = output channel c
    const int n0 = blockIdx.x * 16;

    #pragma unroll
    for (int j = 0; j < 16; ++j)
        in_s[j][t] = inp[(n0 + j) * CC + t];   // NN % 16 == 0
    __syncthreads();

    float acc[16];
    #pragma unroll
    for (int j = 0; j < 16; ++j) acc[j] = 0.f;
    const float bc = b[t];
    #pragma unroll 4
    for (int i = 0; i < CC; ++i) {
        const float wv = w[i * CC + t];
        #pragma unroll
        for (int j = 0; j < 16; ++j) acc[j] = fmaf(in_s[j][i], wv, acc[j]);
    }
    #pragma unroll
    for (int j = 0; j < 16; ++j) s_out[t][j] = acc[j] + bc;
    __syncthreads();

    const int j  = t & 15;             // source row within block
    const int c0 = t >> 4;             // 8 channels per pass
    // destination: permute within 8-block: dest = (j&8) | ((j&3)<<1) | ((j>>2)&1)
    const int dest = (j & 8) | ((j & 3) << 1) | ((j >> 2) & 1);
    #pragma unroll
    for (int cc = 0; cc < CC; cc += 8) {
        const int c = cc + c0;
        g_sup_t[c * NN + n0 + dest] = tf32_rna_f(s_out[c][j]);
    }
}

// ---------------- kernel 2: split-K tf32 HMMA GEMM with register adjacency premix ----
__global__ void __launch_bounds__(256, 1)
k_gemm(const __grid_constant__ CUtensorMap tmap_a,
       const __grid_constant__ CUtensorMap tmap_b,
       const float* __restrict__ att) {
    extern __shared__ __align__(1024) char dsm[];
    __shared__ __align__(8) uint64_t bars[2 * STAGES];

    const int tid  = threadIdx.x;
    const int wid  = tid >> 5;
    const int lane = tid & 31;
    const int g    = lane >> 2;        // group id 0..7
    const int q    = lane & 3;         // thread-in-group
    const int m0   = blockIdx.x * 128;
    const int sidx = blockIdx.y;       // K split index

    const uint32_t dbase = (smem_u32(dsm) + 1023u) & ~1023u;
    const uint32_t barb  = smem_u32(bars);

    if (tid == 0) {
        for (int s = 0; s < STAGES; ++s) {
            MBARRIER_INIT(barb + 8 * s, 1);
            MBARRIER_INIT(barb + 8 * (STAGES + s), 256);
        }
        asm volatile("fence.proxy.async.shared::cta;" ::: "memory");
    }
    __syncthreads();

    const float at0 = att[0], at1 = att[1], at2 = att[2];
    const int nch = (NCHUNK - sidx + NSPLIT - 1) / NSPLIT;

    // ---- producer prologue: fill all stages ----
    if (tid == 0) {
        int pre = (nch < STAGES) ? nch : STAGES;
        for (int i = 0; i < pre; ++i) {
            uint32_t fb = barb + 8 * i;
            uint32_t sb = dbase + i * STAGE_BYTES;
            MBARRIER_EXPECT_TX(fb, (uint32_t)STAGE_BYTES);
            int k0 = (sidx + i * NSPLIT) * KCH;
            #pragma unroll
            for (int t = 0; t < NADJ; ++t)
                TMA_LOAD_3D(sb + t * TILE_BYTES, &tmap_a, k0, m0, t, fb);
            TMA_LOAD_3D(sb + 3 * TILE_BYTES, &tmap_b, k0, 0, 0, fb);
        }
    }

    float acc[2][8][4];
    #pragma unroll
    for (int mi = 0; mi < 2; ++mi)
        #pragma unroll
        for (int ni = 0; ni < 8; ++ni)
            #pragma unroll
            for (int r = 0; r < 4; ++r) acc[mi][ni][r] = 0.f;

    const int wm = wid & 3;            // M sub-tile 0..3 (32 rows each)
    const int wn = wid >> 2;           // N sub-tile 0..1 (64 cols each)
    const uint32_t xo = (uint32_t)g << 2;  // swizzle xor term, in words

    for (int it = 0; it < nch; ++it) {
        const int s  = it % STAGES;
        const int ph = (it / STAGES) & 1;
        MBARRIER_WAIT_PARITY(barb + 8 * s, ph);

        const uint32_t sb = dbase + s * STAGE_BYTES;
        const uint32_t Bb = sb + 3 * TILE_BYTES;

        #pragma unroll
        for (int ks = 0; ks < 4; ++ks) {
            const uint32_t k0x = ((uint32_t)(ks * 8 + q))     ^ xo;  // A: original k order
            const uint32_t k1x = ((uint32_t)(ks * 8 + q + 4)) ^ xo;
            const uint32_t jbx = ((uint32_t)(ks * 8 + 2 * q)) ^ xo;  // B: permuted pair base (even)

            // ---- load 3 adjacency fragment sets, premix, round to tf32 ----
            uint32_t amix[2][4];
            #pragma unroll
            for (int mi = 0; mi < 2; ++mi) {
                const uint32_t rw = (uint32_t)((wm * 32 + mi * 16 + g) * 32);
                uint32_t w0 = (rw + k0x) * 4;           // (g,   k)
                uint32_t w1 = (rw + 256 + k0x) * 4;     // (g+8, k)
                uint32_t w2 = (rw + k1x) * 4;           // (g,   k+4)
                uint32_t w3 = (rw + 256 + k1x) * 4;     // (g+8, k+4)
                #pragma unroll
                for (int p = 0; p < 4; ++p) {
                    uint32_t wp = (p == 0) ? w0 : (p == 1) ? w1 : (p == 2) ? w2 : w3;
                    float v = at0 * lds_f32(sb + wp);
                    v = fmaf(at1, lds_f32(sb + TILE_BYTES + wp), v);
                    v = fmaf(at2, lds_f32(sb + 2 * TILE_BYTES + wp), v);
                    amix[mi][p] = f2tf32(v);
                }
            }

            // ---- B fragments (paired 8B loads) + MMA ----
            #pragma unroll
            for (int ni = 0; ni < 8; ++ni) {
                const uint32_t cw = (uint32_t)((wn * 64 + ni * 8 + g) * 32);
                uint32_t b0, b1;
                lds_b64(Bb + (cw + jbx) * 4, b0, b1);   // b0 = k, b1 = k+4
                mma_tf32(acc[0][ni], amix[0], b0, b1);
                mma_tf32(acc[1][ni], amix[1], b0, b1);
            }
        }

        MBARRIER_ARRIVE(barb + 8 * (STAGES + s));

        if (tid == 0 && it + STAGES < nch) {
            MBARRIER_WAIT_PARITY_RELAXED(barb + 8 * (STAGES + s), (it / STAGES) & 1);
            uint32_t fb = barb + 8 * s;
            MBARRIER_EXPECT_TX(fb, (uint32_t)STAGE_BYTES);
            int k0 = (sidx + (it + STAGES) * NSPLIT) * KCH;
            #pragma unroll
            for (int t = 0; t < NADJ; ++t)
                TMA_LOAD_3D(sb + t * TILE_BYTES, &tmap_a, k0, m0, t, fb);
            TMA_LOAD_3D(sb + 3 * TILE_BYTES, &tmap_b, k0, 0, 0, fb);
        }
    }

    // ---- write split-K partials ----
    float* pbase = &g_part[sidx][0][0];
    #pragma unroll
    for (int mi = 0; mi < 2; ++mi) {
        #pragma unroll
        for (int ni = 0; ni < 8; ++ni) {
            int r = m0 + wm * 32 + mi * 16 + g;
            int c = wn * 64 + ni * 8 + q * 2;
            float2 v0 = make_float2(acc[mi][ni][0], acc[mi][ni][1]);
            float2 v1 = make_float2(acc[mi][ni][2], acc[mi][ni][3]);
            *reinterpret_cast<float2*>(pbase + (size_t)r * CC + c)       = v0;
            *reinterpret_cast<float2*>(pbase + (size_t)(r + 8) * CC + c) = v1;
        }
    }
}

// ---------------- kernel 3: reduce split-K partials + LeakyReLU --------------------
__global__ void __launch_bounds__(256)
k_reduce(float* __restrict__ out) {
    const int idx = blockIdx.x * 256 + threadIdx.x;   // one float4 each
    const int total = NN * CC / 4;
    if (idx >= total) return;
    const int n  = idx / (CC / 4);
    const int c4 = (idx % (CC / 4)) * 4;

    float4 s = make_float4(0.f, 0.f, 0.f, 0.f);
    #pragma unroll
    for (int k = 0; k < NSPLIT; ++k) {
        const float4 v = *reinterpret_cast<const float4*>(&g_part[k][n][c4]);
        s.x += v.x; s.y += v.y; s.z += v.z; s.w += v.w;
    }
    s.x = (s.x >= 0.f) ? s.x : NSLOPE * s.x;
    s.y = (s.y >= 0.f) ? s.y : NSLOPE * s.y;
    s.z = (s.z >= 0.f) ? s.z : NSLOPE * s.z;
    s.w = (s.w >= 0.f) ? s.w : NSLOPE * s.w;
    *reinterpret_cast<float4*>(&out[(size_t)n * CC + c4]) = s;
}

// ---------------- host launch ----------------
typedef CUresult (*PFN_encodeTiled)(
    CUtensorMap*, CUtensorMapDataType, cuuint32_t, void*,
    const cuuint64_t*, const cuuint64_t*, const cuuint32_t*, const cuuint32_t*,
    CUtensorMapInterleave, CUtensorMapSwizzle, CUtensorMapL2promotion,
    CUtensorMapFloatOOBfill);

extern "C" void kernel_launch(void* const* d_in, const int* in_sizes, int n_in,
                              void* d_out, int out_size) {
    const float *inp = nullptr, *adj = nullptr, *att = nullptr, *w = nullptr, *b = nullptr;
    for (int i = 0; i < n_in; ++i) {
        switch (in_sizes[i]) {
            case NN * CC:        inp = (const float*)d_in[i]; break;
            case NADJ * NN * NN: adj = (const float*)d_in[i]; break;
            case NADJ:           att = (const float*)d_in[i]; break;
            case CC * CC:        w   = (const float*)d_in[i]; break;
            case CC:             b   = (const float*)d_in[i]; break;
            default: break;
        }
    }
    float* out = (float*)d_out;

    k_support<<<NN / 16, 128>>>(inp, w, b);

    PFN_encodeTiled enc = nullptr;
    {
        void* p = nullptr;
        cudaDriverEntryPointQueryResult st;
#if CUDART_VERSION >= 12050
        cudaGetDriverEntryPointByVersion("cuTensorMapEncodeTiled", &p, 12000,
                                         cudaEnableDefault, &st);
#else
        cudaGetDriverEntryPoint("cuTensorMapEncodeTiled", &p, cudaEnableDefault, &st);
#endif
        enc = (PFN_encodeTiled)p;
    }
    void* supt_ptr = nullptr;
    cudaGetSymbolAddress(&supt_ptr, g_sup_t);

    CUtensorMap ta, tb;
    cuuint32_t box[3] = {KCH, 128, 1};
    cuuint32_t es[3]  = {1, 1, 1};
    {   // A: adj_set [NADJ][NN][NN], inner dim = K
        cuuint64_t dims[3] = {NN, NN, NADJ};
        cuuint64_t str[2]  = {(cuuint64_t)NN * 4, (cuuint64_t)NN * NN * 4};
        enc(&ta, CU_TENSOR_MAP_DATA_TYPE_FLOAT32, 3, (void*)adj, dims, str, box, es,
            CU_TENSOR_MAP_INTERLEAVE_NONE, CU_TENSOR_MAP_SWIZZLE_128B,
            CU_TENSOR_MAP_L2_PROMOTION_L2_128B, CU_TENSOR_MAP_FLOAT_OOB_FILL_NONE);
    }
    {   // B: g_sup_t [CC][NN] (k-pair permuted), inner dim = K
        cuuint64_t dims[3] = {NN, CC, 1};
        cuuint64_t str[2]  = {(cuuint64_t)NN * 4, (cuuint64_t)CC * NN * 4};
        enc(&tb, CU_TENSOR_MAP_DATA_TYPE_FLOAT32, 3, supt_ptr, dims, str, box, es,
            CU_TENSOR_MAP_INTERLEAVE_NONE, CU_TENSOR_MAP_SWIZZLE_128B,
            CU_TENSOR_MAP_L2_PROMOTION_L2_128B, CU_TENSOR_MAP_FLOAT_OOB_FILL_NONE);
    }

    cudaFuncSetAttribute(k_gemm, cudaFuncAttributeMaxDynamicSharedMemorySize, DYNSMEM);
    dim3 grid(MTILES, NSPLIT);
    k_gemm<<<grid, 256, DYNSMEM>>>(ta, tb, att);

    k_reduce<<<(NN * CC / 4 + 255) / 256, 256>>>(out);
}

// round 5
// speedup vs baseline: 1.0138x; 1.0055x over previous
#include <cuda_runtime.h>
#include <cuda.h>
#include <cstdint>

// ---------------- problem constants ----------------
#define NN     10000
#define NPAD   10016                        // NN padded to 32 (perm scatter stays in-row)
#define CC     128
#define NADJ   3
#define NSLOPE 0.2f

#define KCH     32
#define NCHUNK  ((NN + KCH - 1) / KCH)      // 313
#define NSPLIT  11                          // 79*11=869 CTAs -> ~5.9 waves
#define MTILES  ((NN + 127) / 128)          // 79
#define MPAD    (MTILES * 128)              // 10112

#define TILE_BYTES  (128 * KCH * 4)         // 16 KB
#define STAGE_BYTES (4 * TILE_BYTES)        // 3 A tiles + 1 B tile = 64 KB
#define STAGES      3
#define MIX_BYTES   (128 * KCH * 4)         // 16 KB mixed-A tile
#define DYNSMEM     (STAGES * STAGE_BYTES + 2 * MIX_BYTES + 1024)   // 230400 B

// scratch (static device arrays — zero-initialized, no allocation)
__device__ __align__(1024) float g_sup_t[CC * NPAD];           // supᵀ tf32, block/slot-rotated
__device__ __align__(16)   float g_part[NSPLIT][MPAD][CC];     // split-K partials

// ---------------- helpers ----------------
__device__ __forceinline__ uint32_t smem_u32(const void* p) {
    uint32_t a;
    asm("{ .reg .u64 t; cvta.to.shared.u64 t, %1; cvt.u32.u64 %0, t; }" : "=r"(a) : "l"(p));
    return a;
}
__device__ __forceinline__ float tf32_rna_f(float x) {
    uint32_t u;
    asm("cvt.rna.tf32.f32 %0, %1;" : "=r"(u) : "f"(x));
    return __uint_as_float(u);
}
__device__ __forceinline__ uint32_t f2tf32(float x) {
    uint32_t u;
    asm("cvt.rna.tf32.f32 %0, %1;" : "=r"(u) : "f"(x));
    return u;
}
__device__ __forceinline__ float4 lds_f128(uint32_t a) {
    float4 v;
    asm volatile("ld.shared.v4.f32 {%0,%1,%2,%3}, [%4];"
        : "=f"(v.x), "=f"(v.y), "=f"(v.z), "=f"(v.w) : "r"(a));
    return v;
}
__device__ __forceinline__ void lds_b64(uint32_t a, uint32_t& lo, uint32_t& hi) {
    asm volatile("ld.shared.v2.b32 {%0, %1}, [%2];" : "=r"(lo), "=r"(hi) : "r"(a));
}
__device__ __forceinline__ void sts_b64(uint32_t a, uint32_t lo, uint32_t hi) {
    asm volatile("st.shared.v2.b32 [%0], {%1, %2};" :: "r"(a), "r"(lo), "r"(hi) : "memory");
}

#define MBARRIER_INIT(addr, cnt) \
    asm volatile("mbarrier.init.shared.b64 [%0], %1;" :: "r"(addr), "r"(cnt) : "memory")
#define MBARRIER_EXPECT_TX(addr, bytes) \
    asm volatile("mbarrier.arrive.expect_tx.shared.b64 _, [%0], %1;" :: "r"(addr), "r"(bytes) : "memory")
#define MBARRIER_ARRIVE(addr) \
    asm volatile("mbarrier.arrive.shared.b64 _, [%0];" :: "r"(addr) : "memory")

#define MBARRIER_WAIT_PARITY(mbar, par) do {                                      \
    uint32_t _m = (mbar), _p = (par), _d;                                         \
    asm volatile("{\n\t.reg .pred p;\n\t"                                         \
        "mbarrier.try_wait.parity.acquire.cta.shared::cta.b64 p, [%1], %2;\n\t"   \
        "selp.b32 %0, 1, 0, p;\n\t}" : "=r"(_d) : "r"(_m), "r"(_p) : "memory");   \
    if (!_d) {                                                                    \
        asm volatile("{\n\t.reg .pred P1;\n\t"                                    \
            "W_%=:\n\t"                                                           \
            "mbarrier.try_wait.parity.acquire.cta.shared::cta.b64 P1, [%0], %1, 0x989680;\n\t" \
            "@P1 bra.uni D_%=;\n\t"                                               \
            "bra.uni W_%=;\n\t"                                                   \
            "D_%=:\n\t}" :: "r"(_m), "r"(_p) : "memory");                         \
    } } while (0)

#define MBARRIER_WAIT_PARITY_RELAXED(mbar, par) do {                              \
    uint32_t _m = (mbar), _p = (par), _d;                                         \
    asm volatile("{\n\t.reg .pred p;\n\t"                                         \
        "mbarrier.try_wait.parity.relaxed.cta.shared::cta.b64 p, [%1], %2, 0x989680;\n\t" \
        "selp.b32 %0, 1, 0, p;\n\t}" : "=r"(_d) : "r"(_m), "r"(_p) : "memory");   \
    if (!_d) {                                                                    \
        asm volatile("{\n\t.reg .pred P1;\n\t"                                    \
            "W_%=:\n\t"                                                           \
            "mbarrier.try_wait.parity.relaxed.cta.shared::cta.b64 P1, [%0], %1, 0x989680;\n\t" \
            "@P1 bra.uni D_%=;\n\t"                                               \
            "bra.uni W_%=;\n\t"                                                   \
            "D_%=:\n\t}" :: "r"(_m), "r"(_p) : "memory");                         \
    } } while (0)

#define TMA_LOAD_3D(sa, tmap, x, y, z, mbar)                                      \
    asm volatile("cp.async.bulk.tensor.3d.shared::cta.global.tile.mbarrier::complete_tx::bytes " \
        "[%0], [%1, {%2, %3, %4}], [%5];"                                         \
        :: "r"((uint32_t)(sa)), "l"(tmap), "r"((int)(x)), "r"((int)(y)),          \
           "r"((int)(z)), "r"((uint32_t)(mbar)) : "memory")

// mma.sync m16n8k8 tf32 (baseline PTX, works at compute_103)
__device__ __forceinline__ void mma_tf32(float* c, const uint32_t* A,
                                         uint32_t b0, uint32_t b1) {
    asm volatile(
        "mma.sync.aligned.m16n8k8.row.col.f32.tf32.tf32.f32 "
        "{%0,%1,%2,%3}, {%4,%5,%6,%7}, {%8,%9}, {%0,%1,%2,%3};"
        : "+f"(c[0]), "+f"(c[1]), "+f"(c[2]), "+f"(c[3])
        : "r"(A[0]), "r"(A[1]), "r"(A[2]), "r"(A[3]), "r"(b0), "r"(b1));
}

// ---------------- kernel 1: support = X@W + b ; transposed tf32 copy ---------------
// For each channel c and 32-chunk of n: logical local kk = (ks*8 + p + 4*hi) stored at
// position ((ks+c)&3)*8 + ((2p+2c)&6) + hi  (block/slot rotation -> conflict-free LDS.64
// B fragment loads in k_gemm after TMA SW128 swizzle).
__global__ void __launch_bounds__(128)
k_support(const float* __restrict__ inp, const float* __restrict__ w,
          const float* __restrict__ b) {
    __shared__ float in_s[8][CC];
    __shared__ float s_out[CC][9];
    const int t  = threadIdx.x;        // = output channel c
    const int n0 = blockIdx.x * 8;

    #pragma unroll
    for (int j = 0; j < 8; ++j)
        in_s[j][t] = inp[(n0 + j) * CC + t];   // NN % 8 == 0
    __syncthreads();

    float acc[8];
    #pragma unroll
    for (int j = 0; j < 8; ++j) acc[j] = 0.f;
    const float bc = b[t];
    #pragma unroll 4
    for (int i = 0; i < CC; ++i) {
        const float wv = w[i * CC + t];
        #pragma unroll
        for (int j = 0; j < 8; ++j) acc[j] = fmaf(in_s[j][i], wv, acc[j]);
    }
    #pragma unroll
    for (int j = 0; j < 8; ++j) s_out[t][j] = acc[j] + bc;
    __syncthreads();

    const int j2 = t & 7;
    const int c0 = t >> 3;             // 16 channels per pass
    const int nloc  = (n0 & 31) | j2;  // local index within 32-chunk (n0 % 8 == 0)
    const int ks    = nloc >> 3;
    const int p     = nloc & 3;
    const int hi    = (nloc >> 2) & 1;
    const int nbase = n0 & ~31;
    #pragma unroll
    for (int cc = 0; cc < CC; cc += 16) {
        const int c = cc + c0;
        const int perm = (((ks + c) & 3) << 3) | ((2 * p + 2 * c) & 6) | hi;
        g_sup_t[c * NPAD + nbase + perm] = tf32_rna_f(s_out[c][j2]);
    }
}

// ---------------- kernel 2: split-K tf32 HMMA GEMM, cooperative premix, 512 thr ----
__global__ void __launch_bounds__(512, 1)
k_gemm(const __grid_constant__ CUtensorMap tmap_a,
       const __grid_constant__ CUtensorMap tmap_b,
       const float* __restrict__ att) {
    extern __shared__ __align__(1024) char dsm[];
    __shared__ __align__(8) uint64_t bars[2 * STAGES];

    const int tid  = threadIdx.x;
    const int wid  = tid >> 5;
    const int lane = tid & 31;
    const int g    = lane >> 2;        // 0..7
    const int q    = lane & 3;         // 0..3
    const int m0   = blockIdx.x * 128;
    const int sidx = blockIdx.y;       // K split index

    const uint32_t dbase   = (smem_u32(dsm) + 1023u) & ~1023u;
    const uint32_t mixbase = dbase + STAGES * STAGE_BYTES;
    const uint32_t barb    = smem_u32(bars);

    if (tid == 0) {
        for (int s = 0; s < STAGES; ++s) {
            MBARRIER_INIT(barb + 8 * s, 1);
            MBARRIER_INIT(barb + 8 * (STAGES + s), 512);
        }
        asm volatile("fence.proxy.async.shared::cta;" ::: "memory");
    }
    __syncthreads();

    const float at0 = att[0], at1 = att[1], at2 = att[2];
    const int nch = (NCHUNK - sidx + NSPLIT - 1) / NSPLIT;

    // ---- producer prologue: fill all stages ----
    if (tid == 0) {
        int pre = (nch < STAGES) ? nch : STAGES;
        for (int i = 0; i < pre; ++i) {
            uint32_t fb = barb + 8 * i;
            uint32_t sb = dbase + i * STAGE_BYTES;
            MBARRIER_EXPECT_TX(fb, (uint32_t)STAGE_BYTES);
            int k0 = (sidx + i * NSPLIT) * KCH;
            #pragma unroll
            for (int t = 0; t < NADJ; ++t)
                TMA_LOAD_3D(sb + t * TILE_BYTES, &tmap_a, k0, m0, t, fb);
            TMA_LOAD_3D(sb + 3 * TILE_BYTES, &tmap_b, k0, 0, 0, fb);
        }
    }

    // warp tiling: 16 warps = 4 (M) x 4 (N); each warp 32 rows x 32 cols
    const int wm = wid & 3;
    const int wn = wid >> 2;

    float acc[2][4][4];
    #pragma unroll
    for (int mi = 0; mi < 2; ++mi)
        #pragma unroll
        for (int ni = 0; ni < 4; ++ni)
            #pragma unroll
            for (int r = 0; r < 4; ++r) acc[mi][ni][r] = 0.f;

    // premix assignment: thread -> (row pr, storage block pb)
    const int pr  = tid >> 2;                       // 0..127
    const int pb  = tid & 3;                        // storage block
    const int pks = (pb - pr) & 3;                  // source k-block
    const uint32_t px  = (uint32_t)((pr & 7) << 2); // SW128 word xor for raw tiles
    const uint32_t pw0 = ((uint32_t)(pks * 8)) ^ px;
    const uint32_t pw1 = ((uint32_t)(pks * 8 + 4)) ^ px;
    const uint32_t prow = (uint32_t)pr * 32;
    const uint32_t pdst = prow + (uint32_t)pb * 8;  // + slot(p)
    const uint32_t pslot0 = (uint32_t)((2 * pr) & 6);

    for (int it = 0; it < nch; ++it) {
        const int s  = it % STAGES;
        const int ph = (it / STAGES) & 1;
        MBARRIER_WAIT_PARITY(barb + 8 * s, ph);

        const uint32_t sb   = dbase + s * STAGE_BYTES;
        const uint32_t Bb   = sb + 3 * TILE_BYTES;
        const uint32_t mixb = mixbase + (uint32_t)(it & 1) * MIX_BYTES;

        // ---- cooperative premix: mix 3 adjacency tiles -> tf32 mixed tile ----
        {
            const uint32_t r0 = sb + (prow + pw0) * 4;
            const uint32_t r1 = sb + (prow + pw1) * 4;
            const float4 x0 = lds_f128(r0);
            const float4 x1 = lds_f128(r1);
            const float4 y0 = lds_f128(r0 + TILE_BYTES);
            const float4 y1 = lds_f128(r1 + TILE_BYTES);
            const float4 z0 = lds_f128(r0 + 2 * TILE_BYTES);
            const float4 z1 = lds_f128(r1 + 2 * TILE_BYTES);
            float mv[8];
            mv[0] = fmaf(at2, z0.x, fmaf(at1, y0.x, at0 * x0.x));
            mv[1] = fmaf(at2, z0.y, fmaf(at1, y0.y, at0 * x0.y));
            mv[2] = fmaf(at2, z0.z, fmaf(at1, y0.z, at0 * x0.z));
            mv[3] = fmaf(at2, z0.w, fmaf(at1, y0.w, at0 * x0.w));
            mv[4] = fmaf(at2, z1.x, fmaf(at1, y1.x, at0 * x1.x));
            mv[5] = fmaf(at2, z1.y, fmaf(at1, y1.y, at0 * x1.y));
            mv[6] = fmaf(at2, z1.z, fmaf(at1, y1.z, at0 * x1.z));
            mv[7] = fmaf(at2, z1.w, fmaf(at1, y1.w, at0 * x1.w));
            #pragma unroll
            for (int p = 0; p < 4; ++p) {
                const uint32_t slot = (pslot0 + 2 * (uint32_t)p) & 6;
                sts_b64(mixb + (pdst + slot) * 4, f2tf32(mv[p]), f2tf32(mv[p + 4]));
            }
        }
        __syncthreads();

        // ---- MMA phase ----
        #pragma unroll
        for (int ks = 0; ks < 4; ++ks) {
            const uint32_t koff = (uint32_t)(((((ks + g) & 3) << 3)) | ((2 * q + 2 * g) & 6));
            uint32_t amix[2][4];
            #pragma unroll
            for (int mi = 0; mi < 2; ++mi) {
                const uint32_t wa = ((uint32_t)(wm * 32 + mi * 16 + g) * 32) + koff;
                lds_b64(mixb + wa * 4,         amix[mi][0], amix[mi][2]);  // row r:   (k, k+4)
                lds_b64(mixb + (wa + 256) * 4, amix[mi][1], amix[mi][3]);  // row r+8
            }
            const uint32_t kb = koff ^ ((uint32_t)g << 2);   // B: + hw SW128 xor
            #pragma unroll
            for (int ni = 0; ni < 4; ++ni) {
                const uint32_t wb = ((uint32_t)(wn * 32 + ni * 8 + g) * 32) + kb;
                uint32_t b0, b1;
                lds_b64(Bb + wb * 4, b0, b1);
                mma_tf32(acc[0][ni], amix[0], b0, b1);
                mma_tf32(acc[1][ni], amix[1], b0, b1);
            }
        }

        MBARRIER_ARRIVE(barb + 8 * (STAGES + s));

        if (tid == 0 && it + STAGES < nch) {
            MBARRIER_WAIT_PARITY_RELAXED(barb + 8 * (STAGES + s), (it / STAGES) & 1);
            uint32_t fb = barb + 8 * s;
            MBARRIER_EXPECT_TX(fb, (uint32_t)STAGE_BYTES);
            int k0 = (sidx + (it + STAGES) * NSPLIT) * KCH;
            #pragma unroll
            for (int t = 0; t < NADJ; ++t)
                TMA_LOAD_3D(sb + t * TILE_BYTES, &tmap_a, k0, m0, t, fb);
            TMA_LOAD_3D(sb + 3 * TILE_BYTES, &tmap_b, k0, 0, 0, fb);
        }
    }

    // ---- write split-K partials ----
    float* pbase = &g_part[sidx][0][0];
    #pragma unroll
    for (int mi = 0; mi < 2; ++mi) {
        #pragma unroll
        for (int ni = 0; ni < 4; ++ni) {
            const int r = m0 + wm * 32 + mi * 16 + g;
            const int c = wn * 32 + ni * 8 + q * 2;
            float2 v0 = make_float2(acc[mi][ni][0], acc[mi][ni][1]);
            float2 v1 = make_float2(acc[mi][ni][2], acc[mi][ni][3]);
            *reinterpret_cast<float2*>(pbase + (size_t)r * CC + c)       = v0;
            *reinterpret_cast<float2*>(pbase + (size_t)(r + 8) * CC + c) = v1;
        }
    }
}

// ---------------- kernel 3: reduce split-K partials + LeakyReLU --------------------
__global__ void __launch_bounds__(256)
k_reduce(float* __restrict__ out) {
    const int idx = blockIdx.x * 256 + threadIdx.x;   // one float4 each
    const int total = NN * CC / 4;
    if (idx >= total) return;
    const int n  = idx / (CC / 4);
    const int c4 = (idx % (CC / 4)) * 4;

    float4 s = make_float4(0.f, 0.f, 0.f, 0.f);
    #pragma unroll
    for (int k = 0; k < NSPLIT; ++k) {
        const float4 v = *reinterpret_cast<const float4*>(&g_part[k][n][c4]);
        s.x += v.x; s.y += v.y; s.z += v.z; s.w += v.w;
    }
    s.x = (s.x >= 0.f) ? s.x : NSLOPE * s.x;
    s.y = (s.y >= 0.f) ? s.y : NSLOPE * s.y;
    s.z = (s.z >= 0.f) ? s.z : NSLOPE * s.z;
    s.w = (s.w >= 0.f) ? s.w : NSLOPE * s.w;
    *reinterpret_cast<float4*>(&out[(size_t)n * CC + c4]) = s;
}

// dummy kernel: shifts launch period to 4 so ncu (-s 5 -c 1) profiles k_gemm
__global__ void k_dummy() {}

// ---------------- host launch ----------------
typedef CUresult (*PFN_encodeTiled)(
    CUtensorMap*, CUtensorMapDataType, cuuint32_t, void*,
    const cuuint64_t*, const cuuint64_t*, const cuuint32_t*, const cuuint32_t*,
    CUtensorMapInterleave, CUtensorMapSwizzle, CUtensorMapL2promotion,
    CUtensorMapFloatOOBfill);

extern "C" void kernel_launch(void* const* d_in, const int* in_sizes, int n_in,
                              void* d_out, int out_size) {
    const float *inp = nullptr, *adj = nullptr, *att = nullptr, *w = nullptr, *b = nullptr;
    for (int i = 0; i < n_in; ++i) {
        switch (in_sizes[i]) {
            case NN * CC:        inp = (const float*)d_in[i]; break;
            case NADJ * NN * NN: adj = (const float*)d_in[i]; break;
            case NADJ:           att = (const float*)d_in[i]; break;
            case CC * CC:        w   = (const float*)d_in[i]; break;
            case CC:             b   = (const float*)d_in[i]; break;
            default: break;
        }
    }
    float* out = (float*)d_out;

    k_support<<<NN / 8, 128>>>(inp, w, b);

    PFN_encodeTiled enc = nullptr;
    {
        void* p = nullptr;
        cudaDriverEntryPointQueryResult st;
#if CUDART_VERSION >= 12050
        cudaGetDriverEntryPointByVersion("cuTensorMapEncodeTiled", &p, 12000,
                                         cudaEnableDefault, &st);
#else
        cudaGetDriverEntryPoint("cuTensorMapEncodeTiled", &p, cudaEnableDefault, &st);
#endif
        enc = (PFN_encodeTiled)p;
    }
    void* supt_ptr = nullptr;
    cudaGetSymbolAddress(&supt_ptr, g_sup_t);

    CUtensorMap ta, tb;
    cuuint32_t box[3] = {KCH, 128, 1};
    cuuint32_t es[3]  = {1, 1, 1};
    {   // A: adj_set [NADJ][NN][NN], inner dim = K
        cuuint64_t dims[3] = {NN, NN, NADJ};
        cuuint64_t str[2]  = {(cuuint64_t)NN * 4, (cuuint64_t)NN * NN * 4};
        enc(&ta, CU_TENSOR_MAP_DATA_TYPE_FLOAT32, 3, (void*)adj, dims, str, box, es,
            CU_TENSOR_MAP_INTERLEAVE_NONE, CU_TENSOR_MAP_SWIZZLE_128B,
            CU_TENSOR_MAP_L2_PROMOTION_L2_128B, CU_TENSOR_MAP_FLOAT_OOB_FILL_NONE);
    }
    {   // B: g_sup_t [CC][NPAD] (rotated layout), inner dim = K
        cuuint64_t dims[3] = {NPAD, CC, 1};
        cuuint64_t str[2]  = {(cuuint64_t)NPAD * 4, (cuuint64_t)CC * NPAD * 4};
        enc(&tb, CU_TENSOR_MAP_DATA_TYPE_FLOAT32, 3, supt_ptr, dims, str, box, es,
            CU_TENSOR_MAP_INTERLEAVE_NONE, CU_TENSOR_MAP_SWIZZLE_128B,
            CU_TENSOR_MAP_L2_PROMOTION_L2_128B, CU_TENSOR_MAP_FLOAT_OOB_FILL_NONE);
    }

    cudaFuncSetAttribute(k_gemm, cudaFuncAttributeMaxDynamicSharedMemorySize, DYNSMEM);
    dim3 grid(MTILES, NSPLIT);
    k_gemm<<<grid, 512, DYNSMEM>>>(ta, tb, att);

    k_reduce<<<(NN * CC / 4 + 255) / 256, 256>>>(out);
    k_dummy<<<1, 32>>>();
}